// round 14
// baseline (speedup 1.0000x reference)
#include <cuda_runtime.h>
#include <cuda_bf16.h>
#include <cstdint>
#include <cstddef>

#define BATCH 8
#define SEQ   1024
#define CDIM  768
#define HEADS 12
#define MTOK  (BATCH*SEQ)      // 8192
#define QKVC  (3*CDIM)         // 2304
#define DHEAD 64

// Persistent scratch (device globals — allocation is forbidden)
__device__ __nv_bfloat16 g_x_hi   [(size_t)MTOK * CDIM];
__device__ __nv_bfloat16 g_x_mid  [(size_t)MTOK * CDIM];
__device__ __nv_bfloat16 g_wqkv_hi [(size_t)QKVC * CDIM];
__device__ __nv_bfloat16 g_wqkv_mid[(size_t)QKVC * CDIM];
__device__ __nv_bfloat16 g_wproj_hi [(size_t)CDIM * CDIM];
__device__ __nv_bfloat16 g_wproj_mid[(size_t)CDIM * CDIM];
__device__ __nv_bfloat16 g_qkv_hi [(size_t)MTOK * QKVC];
__device__ __nv_bfloat16 g_qkv_mid[(size_t)MTOK * QKVC];
__device__ __nv_bfloat16 g_ctx_hi [(size_t)MTOK * CDIM];
__device__ __nv_bfloat16 g_ctx_mid[(size_t)MTOK * CDIM];

// ---------------------------------------------------------------------------
__device__ __forceinline__ void mma16816(float* d, const uint32_t* a, const uint32_t* b)
{
    asm volatile(
        "mma.sync.aligned.m16n8k16.row.col.f32.bf16.bf16.f32 "
        "{%0,%1,%2,%3},{%4,%5,%6,%7},{%8,%9},{%0,%1,%2,%3};\n"
        : "+f"(d[0]), "+f"(d[1]), "+f"(d[2]), "+f"(d[3])
        : "r"(a[0]), "r"(a[1]), "r"(a[2]), "r"(a[3]), "r"(b[0]), "r"(b[1]));
}

__device__ __forceinline__ void ldsm_x4(uint32_t* r, uint32_t saddr)
{
    asm volatile("ldmatrix.sync.aligned.m8n8.x4.shared.b16 {%0,%1,%2,%3}, [%4];"
        : "=r"(r[0]), "=r"(r[1]), "=r"(r[2]), "=r"(r[3]) : "r"(saddr));
}

__device__ __forceinline__ void ldsm_x4_t(uint32_t* r, uint32_t saddr)
{
    asm volatile("ldmatrix.sync.aligned.m8n8.x4.trans.shared.b16 {%0,%1,%2,%3}, [%4];"
        : "=r"(r[0]), "=r"(r[1]), "=r"(r[2]), "=r"(r[3]) : "r"(saddr));
}

__device__ __forceinline__ void cp_async16(uint32_t saddr, const void* gptr)
{
    asm volatile("cp.async.cg.shared.global [%0], [%1], 16;"
        :: "r"(saddr), "l"(gptr));
}
#define CP_COMMIT() asm volatile("cp.async.commit_group;" ::: "memory")
#define CP_WAIT0()  asm volatile("cp.async.wait_group 0;" ::: "memory")

__device__ __forceinline__ void cvt_pair(float x, float y, uint32_t& hi, uint32_t& mid)
{
    __nv_bfloat162 h = __floats2bfloat162_rn(x, y);
    float rx = x - __bfloat162float(__low2bfloat16(h));
    float ry = y - __bfloat162float(__high2bfloat16(h));
    __nv_bfloat162 m = __floats2bfloat162_rn(rx, ry);
    hi  = *reinterpret_cast<uint32_t*>(&h);
    mid = *reinterpret_cast<uint32_t*>(&m);
}

// ---------------------------------------------------------------------------
// Fused prep: split x/wqkv/wproj into hi/mid planes. One launch.
// ---------------------------------------------------------------------------
#define N4_X   (MTOK * CDIM / 4)
#define N4_WQ  (QKVC * CDIM / 4)
#define N4_WP  (CDIM * CDIM / 4)

__global__ __launch_bounds__(256) void prep_kernel(
    const float* __restrict__ x, const float* __restrict__ wq,
    const float* __restrict__ wp,
    __nv_bfloat16* __restrict__ x_hi, __nv_bfloat16* __restrict__ x_mid,
    __nv_bfloat16* __restrict__ wq_hi, __nv_bfloat16* __restrict__ wq_mid,
    __nv_bfloat16* __restrict__ wp_hi, __nv_bfloat16* __restrict__ wp_mid)
{
    int i = blockIdx.x * blockDim.x + threadIdx.x;
    const float* src; __nv_bfloat16 *hi, *mid; int off;
    if (i < N4_X)                        { src = x;  hi = x_hi;  mid = x_mid;  off = 0; }
    else if (i < N4_X + N4_WQ)           { src = wq; hi = wq_hi; mid = wq_mid; off = N4_X; }
    else if (i < N4_X + N4_WQ + N4_WP)   { src = wp; hi = wp_hi; mid = wp_mid; off = N4_X + N4_WQ; }
    else return;
    int j = i - off;
    float4 v = ((const float4*)src)[j];
    uint32_t h0, m0, h1, m1;
    cvt_pair(v.x, v.y, h0, m0);
    cvt_pair(v.z, v.w, h1, m1);
    ((uint2*)hi)[j]  = make_uint2(h0, h1);
    ((uint2*)mid)[j] = make_uint2(m0, m1);
}

// ---------------------------------------------------------------------------
// GEMM on pre-split bf16 hi/mid operands (QKV + proj).
// R13: BM=128, BN=64, warp tile 32x32 (MF=2,NF=4) -> ~80 regs -> 3 CTAs/SM.
// ---------------------------------------------------------------------------
template<int OUT>   // 0: fp32+bias, 2: hi/mid planes
__global__ __launch_bounds__(256, 3) void gemm3(
    const __nv_bfloat16* __restrict__ Ahi, const __nv_bfloat16* __restrict__ Amid, int lda,
    const __nv_bfloat16* __restrict__ Bhi, const __nv_bfloat16* __restrict__ Bmid, int ldb,
    float* __restrict__ Cf, __nv_bfloat16* __restrict__ Chi, __nv_bfloat16* __restrict__ Cmid,
    int ldc, int K, const float* __restrict__ bias)
{
    constexpr int BM = 128, BN = 64, WM = 32, WN = 32;
    constexpr int BK = 32, BKP = 40;
    constexpr int MW = BM / WM;      // 4 warps along M
    constexpr int MF = WM / 16;      // 2
    constexpr int NF = WN / 8;       // 4

    extern __shared__ __nv_bfloat16 sm[];
    __nv_bfloat16* Asm = sm;                     // [2][2][128][40]
    __nv_bfloat16* Bsm = sm + 4 * BM * BKP;      // [2][2][64][40]
    const uint32_t asm_u32 = (uint32_t)__cvta_generic_to_shared(Asm);
    const uint32_t bsm_u32 = (uint32_t)__cvta_generic_to_shared(Bsm);

    const int m0 = blockIdx.y * BM, n0 = blockIdx.x * BN;
    const int tid = threadIdx.x, w = tid >> 5, lane = tid & 31;
    const int wm = w % MW, wn = w / MW;
    const int g = lane >> 2, t2 = (lane & 3) * 2;

    const int a_row_off = ((lane >> 3) & 1) * 8 + (lane & 7);
    const int a_col_off = (lane >> 4) * 8;
    const int b_row_off = (lane >> 4) * 8 + (lane & 7);
    const int b_col_off = ((lane >> 3) & 1) * 8;

    float acc[MF][NF][4];
#pragma unroll
    for (int i = 0; i < MF; i++)
#pragma unroll
        for (int j = 0; j < NF; j++)
#pragma unroll
            for (int q = 0; q < 4; q++) acc[i][j][q] = 0.0f;

    const int a_row = tid >> 1, a_seg = (tid & 1) * 16;      // 2 thr/row, 16 elems
    const int b_row = tid >> 2, b_seg = (tid & 3) * 8;       // 4 thr/row, 8 elems

    auto issue_tile = [&](int kt, int bb) {
        const __nv_bfloat16* ph = Ahi + (size_t)(m0 + a_row) * lda + kt + a_seg;
        const __nv_bfloat16* pm = Amid + (size_t)(m0 + a_row) * lda + kt + a_seg;
        uint32_t d0 = asm_u32 + (uint32_t)((((bb * 2 + 0) * BM + a_row) * BKP + a_seg) * 2);
        uint32_t d1 = asm_u32 + (uint32_t)((((bb * 2 + 1) * BM + a_row) * BKP + a_seg) * 2);
        cp_async16(d0, ph);      cp_async16(d0 + 16, ph + 8);
        cp_async16(d1, pm);      cp_async16(d1 + 16, pm + 8);
        const __nv_bfloat16* qh = Bhi + (size_t)(n0 + b_row) * ldb + kt + b_seg;
        const __nv_bfloat16* qm = Bmid + (size_t)(n0 + b_row) * ldb + kt + b_seg;
        uint32_t e0 = bsm_u32 + (uint32_t)((((bb * 2 + 0) * BN + b_row) * BKP + b_seg) * 2);
        uint32_t e1 = bsm_u32 + (uint32_t)((((bb * 2 + 1) * BN + b_row) * BKP + b_seg) * 2);
        cp_async16(e0, qh);
        cp_async16(e1, qm);
    };

    const int iters = K / BK;
    issue_tile(0, 0);
    CP_COMMIT(); CP_WAIT0(); __syncthreads();

    for (int it = 0; it < iters; it++) {
        const int buf = it & 1;
        const bool more = (it + 1 < iters);
        if (more) { issue_tile((it + 1) * BK, buf ^ 1); CP_COMMIT(); }

#pragma unroll
        for (int ks = 0; ks < BK; ks += 16) {
            uint32_t af[2][MF][4], bf[2][NF][2];
#pragma unroll
            for (int s = 0; s < 2; s++) {
#pragma unroll
                for (int i = 0; i < MF; i++) {
                    int row = wm * WM + i * 16 + a_row_off;
                    uint32_t addr = asm_u32 +
                        (uint32_t)((((buf * 2 + s) * BM + row) * BKP + ks + a_col_off) * 2);
                    ldsm_x4(af[s][i], addr);
                }
#pragma unroll
                for (int jj = 0; jj < NF / 2; jj++) {
                    int row = wn * WN + jj * 16 + b_row_off;
                    uint32_t addr = bsm_u32 +
                        (uint32_t)((((buf * 2 + s) * BN + row) * BKP + ks + b_col_off) * 2);
                    uint32_t r[4];
                    ldsm_x4(r, addr);
                    bf[s][jj * 2 + 0][0] = r[0]; bf[s][jj * 2 + 0][1] = r[1];
                    bf[s][jj * 2 + 1][0] = r[2]; bf[s][jj * 2 + 1][1] = r[3];
                }
            }
#pragma unroll
            for (int i = 0; i < MF; i++)
#pragma unroll
                for (int j = 0; j < NF; j++) {
                    mma16816(acc[i][j], af[0][i], bf[0][j]);
                    mma16816(acc[i][j], af[0][i], bf[1][j]);
                    mma16816(acc[i][j], af[1][i], bf[0][j]);
                }
        }
        if (more) CP_WAIT0();
        __syncthreads();
    }

#pragma unroll
    for (int i = 0; i < MF; i++) {
        int r = m0 + wm * WM + i * 16 + g;
#pragma unroll
        for (int j = 0; j < NF; j++) {
            int c = n0 + wn * WN + j * 8 + t2;
            if (OUT == 2) {
                uint32_t h, mm;
                cvt_pair(acc[i][j][0], acc[i][j][1], h, mm);
                *(uint32_t*)&Chi[(size_t)r * ldc + c] = h;
                *(uint32_t*)&Cmid[(size_t)r * ldc + c] = mm;
                cvt_pair(acc[i][j][2], acc[i][j][3], h, mm);
                *(uint32_t*)&Chi[(size_t)(r + 8) * ldc + c] = h;
                *(uint32_t*)&Cmid[(size_t)(r + 8) * ldc + c] = mm;
            } else {
                float b0 = bias ? bias[c] : 0.0f;
                float b1 = bias ? bias[c + 1] : 0.0f;
                *(float2*)&Cf[(size_t)r * ldc + c] =
                    make_float2(acc[i][j][0] + b0, acc[i][j][1] + b1);
                *(float2*)&Cf[(size_t)(r + 8) * ldc + c] =
                    make_float2(acc[i][j][2] + b0, acc[i][j][3] + b1);
            }
        }
    }
}

// ---------------------------------------------------------------------------
// Fused attention (unchanged from R12 — proven at 1.58e-5).
// ---------------------------------------------------------------------------
#define BMQ 128
#define KT  64
#define NKT (SEQ/KT)
#define QP  72

__global__ __launch_bounds__(256, 2) void fused_attn(
    const __nv_bfloat16* __restrict__ qkv_hi,
    const __nv_bfloat16* __restrict__ qkv_mid,
    float* __restrict__ attn,
    __nv_bfloat16* __restrict__ ctx_hi,
    __nv_bfloat16* __restrict__ ctx_mid)
{
    extern __shared__ __nv_bfloat16 sm[];
    __nv_bfloat16* Qs = sm;                  // [2][128][72]
    __nv_bfloat16* Ks = Qs + 2 * BMQ * QP;   // [2][2][64][72]
    __nv_bfloat16* Vs = Ks + 4 * KT * QP;    // [2][2][64][72]
    const uint32_t qs_u = (uint32_t)__cvta_generic_to_shared(Qs);
    const uint32_t ks_u = (uint32_t)__cvta_generic_to_shared(Ks);
    const uint32_t vs_u = (uint32_t)__cvta_generic_to_shared(Vs);

    const int nb = blockIdx.x, h = blockIdx.y, b = blockIdx.z;
    const int tid = threadIdx.x, w = tid >> 5, lane = tid & 31;
    const int g = lane >> 2, t2 = (lane & 3) * 2;

    const size_t tokbase = (size_t)b * SEQ;
    const int qoff = h * DHEAD, koff = CDIM + h * DHEAD, voff = 2 * CDIM + h * DHEAD;

    const int a_row_off = ((lane >> 3) & 1) * 8 + (lane & 7);
    const int a_col_off = (lane >> 4) * 8;
    const int b_row_off = (lane >> 4) * 8 + (lane & 7);
    const int b_col_off = ((lane >> 3) & 1) * 8;
    const int bt_k_off  = ((lane >> 3) & 1) * 8 + (lane & 7);
    const int bt_n_off  = (lane >> 4) * 8;

    const int q_row = tid >> 1, q_seg = (tid & 1) * 32;    // Q staging
    const int kv_row = tid >> 2, kv_seg = (tid & 3) * 16;  // K/V staging

    // stage Q (once)
    {
        const __nv_bfloat16* qh = qkv_hi + (tokbase + nb * BMQ + q_row) * QKVC + qoff + q_seg;
        const __nv_bfloat16* qm = qkv_mid + (tokbase + nb * BMQ + q_row) * QKVC + qoff + q_seg;
        uint32_t d0 = qs_u + (uint32_t)(((0 * BMQ + q_row) * QP + q_seg) * 2);
        uint32_t d1 = qs_u + (uint32_t)(((1 * BMQ + q_row) * QP + q_seg) * 2);
#pragma unroll
        for (int e = 0; e < 32; e += 8) {
            cp_async16(d0 + 2 * e, qh + e);
            cp_async16(d1 + 2 * e, qm + e);
        }
    }

    auto issue_kv = [&](int kt2, int bb, bool withV) {
        const size_t tok = tokbase + kt2 * KT + kv_row;
        const __nv_bfloat16* kh = qkv_hi + tok * QKVC + koff + kv_seg;
        const __nv_bfloat16* km = qkv_mid + tok * QKVC + koff + kv_seg;
        uint32_t d0 = ks_u + (uint32_t)((((bb * 2 + 0) * KT + kv_row) * QP + kv_seg) * 2);
        uint32_t d1 = ks_u + (uint32_t)((((bb * 2 + 1) * KT + kv_row) * QP + kv_seg) * 2);
        cp_async16(d0, kh);      cp_async16(d0 + 16, kh + 8);
        cp_async16(d1, km);      cp_async16(d1 + 16, km + 8);
        if (withV) {
            const __nv_bfloat16* vh = qkv_hi + tok * QKVC + voff + kv_seg;
            const __nv_bfloat16* vm = qkv_mid + tok * QKVC + voff + kv_seg;
            uint32_t e0 = vs_u + (uint32_t)((((bb * 2 + 0) * KT + kv_row) * QP + kv_seg) * 2);
            uint32_t e1 = vs_u + (uint32_t)((((bb * 2 + 1) * KT + kv_row) * QP + kv_seg) * 2);
            cp_async16(e0, vh);      cp_async16(e0 + 16, vh + 8);
            cp_async16(e1, vm);      cp_async16(e1 + 16, vm + 8);
        }
    };

    float sacc[8][4];
    auto compute_S = [&](int buf) {
#pragma unroll
        for (int j = 0; j < 8; j++)
#pragma unroll
            for (int q = 0; q < 4; q++) sacc[j][q] = 0.0f;
#pragma unroll
        for (int ks = 0; ks < 4; ks++) {
            uint32_t af[2][4];
#pragma unroll
            for (int s = 0; s < 2; s++) {
                int row = w * 16 + a_row_off;
                ldsm_x4(af[s], qs_u +
                    (uint32_t)(((s * BMQ + row) * QP + ks * 16 + a_col_off) * 2));
            }
#pragma unroll
            for (int jj = 0; jj < 4; jj++) {
                uint32_t bh[4], bm[4];
                int row = jj * 16 + b_row_off;
                int col = ks * 16 + b_col_off;
                ldsm_x4(bh, ks_u + (uint32_t)((((buf * 2 + 0) * KT + row) * QP + col) * 2));
                ldsm_x4(bm, ks_u + (uint32_t)((((buf * 2 + 1) * KT + row) * QP + col) * 2));
                uint32_t b0h[2] = { bh[0], bh[1] }, b1h[2] = { bh[2], bh[3] };
                uint32_t b0m[2] = { bm[0], bm[1] }, b1m[2] = { bm[2], bm[3] };
                mma16816(sacc[jj * 2 + 0], af[0], b0h);
                mma16816(sacc[jj * 2 + 0], af[0], b0m);
                mma16816(sacc[jj * 2 + 0], af[1], b0h);
                mma16816(sacc[jj * 2 + 1], af[0], b1h);
                mma16816(sacc[jj * 2 + 1], af[0], b1m);
                mma16816(sacc[jj * 2 + 1], af[1], b1h);
            }
        }
    };

    float U[8][4];
#pragma unroll
    for (int j = 0; j < 8; j++)
#pragma unroll
        for (int q = 0; q < 4; q++) U[j][q] = 0.0f;
    float rs0 = 0.0f, rs1 = 0.0f;

    // ---------------- Phase 1 ----------------
    issue_kv(0, 0, true);
    CP_COMMIT(); CP_WAIT0(); __syncthreads();

    for (int kt = 0; kt < NKT; kt++) {
        const int buf = kt & 1;
        const bool more = (kt + 1 < NKT);
        if (more) { issue_kv(kt + 1, buf ^ 1, true); CP_COMMIT(); }

        compute_S(buf);

#pragma unroll
        for (int j = 0; j < 8; j++) {
            sacc[j][0] = __expf(0.125f * sacc[j][0]);
            sacc[j][1] = __expf(0.125f * sacc[j][1]);
            sacc[j][2] = __expf(0.125f * sacc[j][2]);
            sacc[j][3] = __expf(0.125f * sacc[j][3]);
            rs0 += sacc[j][0] + sacc[j][1];
            rs1 += sacc[j][2] + sacc[j][3];
        }

        // U += E @ V  (C-frag -> A-frag reuse)
#pragma unroll
        for (int ks = 0; ks < 4; ks++) {
            uint32_t ah[4], am[4];
            cvt_pair(sacc[2 * ks][0],     sacc[2 * ks][1],     ah[0], am[0]);
            cvt_pair(sacc[2 * ks][2],     sacc[2 * ks][3],     ah[1], am[1]);
            cvt_pair(sacc[2 * ks + 1][0], sacc[2 * ks + 1][1], ah[2], am[2]);
            cvt_pair(sacc[2 * ks + 1][2], sacc[2 * ks + 1][3], ah[3], am[3]);
#pragma unroll
            for (int jv = 0; jv < 4; jv++) {
                uint32_t rh[4], rm[4];
                int kR = ks * 16 + bt_k_off;
                int nB = jv * 16 + bt_n_off;
                ldsm_x4_t(rh, vs_u + (uint32_t)((((buf * 2 + 0) * KT + kR) * QP + nB) * 2));
                ldsm_x4_t(rm, vs_u + (uint32_t)((((buf * 2 + 1) * KT + kR) * QP + nB) * 2));
                uint32_t bh0[2] = { rh[0], rh[1] }, bh1[2] = { rh[2], rh[3] };
                uint32_t bm0[2] = { rm[0], rm[1] }, bm1[2] = { rm[2], rm[3] };
                mma16816(U[jv * 2 + 0], ah, bh0);
                mma16816(U[jv * 2 + 0], ah, bm0);
                mma16816(U[jv * 2 + 0], am, bh0);
                mma16816(U[jv * 2 + 1], ah, bh1);
                mma16816(U[jv * 2 + 1], ah, bm1);
                mma16816(U[jv * 2 + 1], am, bh1);
            }
        }

        if (more) CP_WAIT0();
        __syncthreads();
    }

    rs0 += __shfl_xor_sync(0xffffffffu, rs0, 1);
    rs0 += __shfl_xor_sync(0xffffffffu, rs0, 2);
    rs1 += __shfl_xor_sync(0xffffffffu, rs1, 1);
    rs1 += __shfl_xor_sync(0xffffffffu, rs1, 2);
    const float inv0 = 1.0f / rs0;
    const float inv1 = 1.0f / rs1;

    // ctx = U * inv -> hi/mid planes
    {
        const size_t tok = tokbase + nb * BMQ + w * 16 + g;
        __nv_bfloat16* ch = ctx_hi + tok * CDIM + h * DHEAD;
        __nv_bfloat16* cm = ctx_mid + tok * CDIM + h * DHEAD;
#pragma unroll
        for (int jv = 0; jv < 8; jv++) {
            int c = jv * 8 + t2;
            uint32_t hh, mm;
            cvt_pair(U[jv][0] * inv0, U[jv][1] * inv0, hh, mm);
            *(uint32_t*)&ch[c] = hh;
            *(uint32_t*)&cm[c] = mm;
            cvt_pair(U[jv][2] * inv1, U[jv][3] * inv1, hh, mm);
            *(uint32_t*)&ch[8 * CDIM + c] = hh;
            *(uint32_t*)&cm[8 * CDIM + c] = mm;
        }
    }

    // ---------------- Phase 2: recompute S, write P ----------------
    issue_kv(0, 0, false);
    CP_COMMIT(); CP_WAIT0(); __syncthreads();

    float* dst0 = attn + ((size_t)(b * HEADS + h) * SEQ + nb * BMQ + w * 16 + g) * SEQ;
    float* dst1 = dst0 + 8 * SEQ;

    for (int kt = 0; kt < NKT; kt++) {
        const int buf = kt & 1;
        const bool more = (kt + 1 < NKT);
        if (more) { issue_kv(kt + 1, buf ^ 1, false); CP_COMMIT(); }

        compute_S(buf);

#pragma unroll
        for (int j = 0; j < 8; j++) {
            int c = kt * KT + j * 8 + t2;
            float e0 = __expf(0.125f * sacc[j][0]);
            float e1 = __expf(0.125f * sacc[j][1]);
            float e2 = __expf(0.125f * sacc[j][2]);
            float e3 = __expf(0.125f * sacc[j][3]);
            *(float2*)&dst0[c] = make_float2(e0 * inv0, e1 * inv0);
            *(float2*)&dst1[c] = make_float2(e2 * inv1, e3 * inv1);
        }

        if (more) CP_WAIT0();
        __syncthreads();
    }
}

// ---------------------------------------------------------------------------
extern "C" void kernel_launch(void* const* d_in, const int* in_sizes, int n_in,
                              void* d_out, int out_size)
{
    const float* x      = (const float*)d_in[0];
    const float* qkv_w  = (const float*)d_in[1];
    const float* proj_w = (const float*)d_in[2];
    const float* proj_b = (const float*)d_in[3];

    float* out_proj = (float*)d_out;
    float* out_attn = (float*)d_out + (size_t)MTOK * CDIM;

    __nv_bfloat16 *x_hi, *x_mid, *wq_hi, *wq_mid, *wp_hi, *wp_mid;
    __nv_bfloat16 *qkv_hi, *qkv_mid, *ctx_hi, *ctx_mid;
    cudaGetSymbolAddress((void**)&x_hi,   g_x_hi);
    cudaGetSymbolAddress((void**)&x_mid,  g_x_mid);
    cudaGetSymbolAddress((void**)&wq_hi,  g_wqkv_hi);
    cudaGetSymbolAddress((void**)&wq_mid, g_wqkv_mid);
    cudaGetSymbolAddress((void**)&wp_hi,  g_wproj_hi);
    cudaGetSymbolAddress((void**)&wp_mid, g_wproj_mid);
    cudaGetSymbolAddress((void**)&qkv_hi, g_qkv_hi);
    cudaGetSymbolAddress((void**)&qkv_mid,g_qkv_mid);
    cudaGetSymbolAddress((void**)&ctx_hi, g_ctx_hi);
    cudaGetSymbolAddress((void**)&ctx_mid,g_ctx_mid);

    constexpr int SM_KC = (4 * 128 * 40 + 4 * 64 * 40) * 2;                 // 61440 B
    constexpr int SM_FA = (2 * BMQ * QP + 4 * KT * QP + 4 * KT * QP) * 2;   // 110592 B

    cudaFuncSetAttribute((const void*)gemm3<2>,
                         cudaFuncAttributeMaxDynamicSharedMemorySize, SM_KC);
    cudaFuncSetAttribute((const void*)gemm3<0>,
                         cudaFuncAttributeMaxDynamicSharedMemorySize, SM_KC);
    cudaFuncSetAttribute((const void*)fused_attn,
                         cudaFuncAttributeMaxDynamicSharedMemorySize, SM_FA);

    // 0) split inputs to hi/mid planes
    {
        int total = N4_X + N4_WQ + N4_WP;
        prep_kernel<<<(total + 255) / 256, 256>>>(
            x, qkv_w, proj_w, x_hi, x_mid, wq_hi, wq_mid, wp_hi, wp_mid);
    }

    // 1) QKV GEMM -> split planes
    gemm3<2><<<dim3(QKVC / 64, MTOK / 128), 256, SM_KC>>>(
        x_hi, x_mid, CDIM, wq_hi, wq_mid, CDIM,
        nullptr, qkv_hi, qkv_mid, QKVC, CDIM, nullptr);

    // 2) fused attention: S + softmax + attn write + PV
    fused_attn<<<dim3(SEQ / BMQ, HEADS, BATCH), 256, SM_FA>>>(
        qkv_hi, qkv_mid, out_attn, ctx_hi, ctx_mid);

    // 3) proj: ctx @ proj_w^T + bias -> out
    gemm3<0><<<dim3(CDIM / 64, MTOK / 128), 256, SM_KC>>>(
        ctx_hi, ctx_mid, CDIM, wp_hi, wp_mid, CDIM,
        out_proj, nullptr, nullptr, CDIM, CDIM, proj_b);
}

// round 16
// speedup vs baseline: 1.0119x; 1.0119x over previous
#include <cuda_runtime.h>
#include <cuda_bf16.h>
#include <cstdint>
#include <cstddef>

#define BATCH 8
#define SEQ   1024
#define CDIM  768
#define HEADS 12
#define MTOK  (BATCH*SEQ)      // 8192
#define QKVC  (3*CDIM)         // 2304
#define DHEAD 64

// Persistent scratch (device globals — allocation is forbidden)
__device__ __nv_bfloat16 g_x_hi   [(size_t)MTOK * CDIM];
__device__ __nv_bfloat16 g_x_mid  [(size_t)MTOK * CDIM];
__device__ __nv_bfloat16 g_wqkv_hi [(size_t)QKVC * CDIM];
__device__ __nv_bfloat16 g_wqkv_mid[(size_t)QKVC * CDIM];
__device__ __nv_bfloat16 g_wproj_hi [(size_t)CDIM * CDIM];
__device__ __nv_bfloat16 g_wproj_mid[(size_t)CDIM * CDIM];
__device__ __nv_bfloat16 g_qkv_hi [(size_t)MTOK * QKVC];
__device__ __nv_bfloat16 g_qkv_mid[(size_t)MTOK * QKVC];
__device__ __nv_bfloat16 g_ctx_hi [(size_t)MTOK * CDIM];
__device__ __nv_bfloat16 g_ctx_mid[(size_t)MTOK * CDIM];

// ---------------------------------------------------------------------------
__device__ __forceinline__ void mma16816(float* d, const uint32_t* a, const uint32_t* b)
{
    asm volatile(
        "mma.sync.aligned.m16n8k16.row.col.f32.bf16.bf16.f32 "
        "{%0,%1,%2,%3},{%4,%5,%6,%7},{%8,%9},{%0,%1,%2,%3};\n"
        : "+f"(d[0]), "+f"(d[1]), "+f"(d[2]), "+f"(d[3])
        : "r"(a[0]), "r"(a[1]), "r"(a[2]), "r"(a[3]), "r"(b[0]), "r"(b[1]));
}

__device__ __forceinline__ void ldsm_x4(uint32_t* r, uint32_t saddr)
{
    asm volatile("ldmatrix.sync.aligned.m8n8.x4.shared.b16 {%0,%1,%2,%3}, [%4];"
        : "=r"(r[0]), "=r"(r[1]), "=r"(r[2]), "=r"(r[3]) : "r"(saddr));
}

__device__ __forceinline__ void ldsm_x4_t(uint32_t* r, uint32_t saddr)
{
    asm volatile("ldmatrix.sync.aligned.m8n8.x4.trans.shared.b16 {%0,%1,%2,%3}, [%4];"
        : "=r"(r[0]), "=r"(r[1]), "=r"(r[2]), "=r"(r[3]) : "r"(saddr));
}

__device__ __forceinline__ void cp_async16(uint32_t saddr, const void* gptr)
{
    asm volatile("cp.async.cg.shared.global [%0], [%1], 16;"
        :: "r"(saddr), "l"(gptr));
}
#define CP_COMMIT() asm volatile("cp.async.commit_group;" ::: "memory")
#define CP_WAIT0()  asm volatile("cp.async.wait_group 0;" ::: "memory")

__device__ __forceinline__ void cvt_pair(float x, float y, uint32_t& hi, uint32_t& mid)
{
    __nv_bfloat162 h = __floats2bfloat162_rn(x, y);
    float rx = x - __bfloat162float(__low2bfloat16(h));
    float ry = y - __bfloat162float(__high2bfloat16(h));
    __nv_bfloat162 m = __floats2bfloat162_rn(rx, ry);
    hi  = *reinterpret_cast<uint32_t*>(&h);
    mid = *reinterpret_cast<uint32_t*>(&m);
}

// ---------------------------------------------------------------------------
// Fused prep: split x/wqkv/wproj into hi/mid planes. One launch.
// ---------------------------------------------------------------------------
#define N4_X   (MTOK * CDIM / 4)
#define N4_WQ  (QKVC * CDIM / 4)
#define N4_WP  (CDIM * CDIM / 4)

__global__ __launch_bounds__(256) void prep_kernel(
    const float* __restrict__ x, const float* __restrict__ wq,
    const float* __restrict__ wp,
    __nv_bfloat16* __restrict__ x_hi, __nv_bfloat16* __restrict__ x_mid,
    __nv_bfloat16* __restrict__ wq_hi, __nv_bfloat16* __restrict__ wq_mid,
    __nv_bfloat16* __restrict__ wp_hi, __nv_bfloat16* __restrict__ wp_mid)
{
    int i = blockIdx.x * blockDim.x + threadIdx.x;
    const float* src; __nv_bfloat16 *hi, *mid; int off;
    if (i < N4_X)                        { src = x;  hi = x_hi;  mid = x_mid;  off = 0; }
    else if (i < N4_X + N4_WQ)           { src = wq; hi = wq_hi; mid = wq_mid; off = N4_X; }
    else if (i < N4_X + N4_WQ + N4_WP)   { src = wp; hi = wp_hi; mid = wp_mid; off = N4_X + N4_WQ; }
    else return;
    int j = i - off;
    float4 v = ((const float4*)src)[j];
    uint32_t h0, m0, h1, m1;
    cvt_pair(v.x, v.y, h0, m0);
    cvt_pair(v.z, v.w, h1, m1);
    ((uint2*)hi)[j]  = make_uint2(h0, h1);
    ((uint2*)mid)[j] = make_uint2(m0, m1);
}

// ---------------------------------------------------------------------------
// GEMM on pre-split bf16 hi/mid operands (QKV + proj). R12 config (proven),
// with term-major MMA issue order: consecutive MMAs hit different
// accumulators (no RAW chains); per-accumulator order unchanged (hh,hm,mh)
// so results are bit-identical to R12.
// ---------------------------------------------------------------------------
template<int OUT>   // 0: fp32+bias, 2: hi/mid planes
__global__ __launch_bounds__(256, 2) void gemm3(
    const __nv_bfloat16* __restrict__ Ahi, const __nv_bfloat16* __restrict__ Amid, int lda,
    const __nv_bfloat16* __restrict__ Bhi, const __nv_bfloat16* __restrict__ Bmid, int ldb,
    float* __restrict__ Cf, __nv_bfloat16* __restrict__ Chi, __nv_bfloat16* __restrict__ Cmid,
    int ldc, int K, const float* __restrict__ bias)
{
    constexpr int BM = 128, BN = 128, WM = 64, WN = 32;
    constexpr int BK = 32, BKP = 40;
    constexpr int MW = BM / WM, MF = WM / 16, NF = WN / 8;

    extern __shared__ __nv_bfloat16 sm[];
    __nv_bfloat16* Asm = sm;
    __nv_bfloat16* Bsm = sm + 4 * BM * BKP;
    const uint32_t asm_u32 = (uint32_t)__cvta_generic_to_shared(Asm);
    const uint32_t bsm_u32 = (uint32_t)__cvta_generic_to_shared(Bsm);

    const int m0 = blockIdx.y * BM, n0 = blockIdx.x * BN;
    const int tid = threadIdx.x, w = tid >> 5, lane = tid & 31;
    const int wm = w % MW, wn = w / MW;
    const int g = lane >> 2, t2 = (lane & 3) * 2;

    const int a_row_off = ((lane >> 3) & 1) * 8 + (lane & 7);
    const int a_col_off = (lane >> 4) * 8;
    const int b_row_off = (lane >> 4) * 8 + (lane & 7);
    const int b_col_off = ((lane >> 3) & 1) * 8;

    float acc[MF][NF][4];
#pragma unroll
    for (int i = 0; i < MF; i++)
#pragma unroll
        for (int j = 0; j < NF; j++)
#pragma unroll
            for (int q = 0; q < 4; q++) acc[i][j][q] = 0.0f;

    const int a_row = tid >> 1, a_seg = (tid & 1) * 16;

    auto issue_tile = [&](int kt, int bb) {
        const __nv_bfloat16* ph = Ahi + (size_t)(m0 + a_row) * lda + kt + a_seg;
        const __nv_bfloat16* pm = Amid + (size_t)(m0 + a_row) * lda + kt + a_seg;
        uint32_t d0 = asm_u32 + (uint32_t)((((bb * 2 + 0) * BM + a_row) * BKP + a_seg) * 2);
        uint32_t d1 = asm_u32 + (uint32_t)((((bb * 2 + 1) * BM + a_row) * BKP + a_seg) * 2);
        cp_async16(d0, ph);      cp_async16(d0 + 16, ph + 8);
        cp_async16(d1, pm);      cp_async16(d1 + 16, pm + 8);
        const __nv_bfloat16* qh = Bhi + (size_t)(n0 + a_row) * ldb + kt + a_seg;
        const __nv_bfloat16* qm = Bmid + (size_t)(n0 + a_row) * ldb + kt + a_seg;
        uint32_t e0 = bsm_u32 + (uint32_t)((((bb * 2 + 0) * BN + a_row) * BKP + a_seg) * 2);
        uint32_t e1 = bsm_u32 + (uint32_t)((((bb * 2 + 1) * BN + a_row) * BKP + a_seg) * 2);
        cp_async16(e0, qh);      cp_async16(e0 + 16, qh + 8);
        cp_async16(e1, qm);      cp_async16(e1 + 16, qm + 8);
    };

    const int iters = K / BK;
    issue_tile(0, 0);
    CP_COMMIT(); CP_WAIT0(); __syncthreads();

    for (int it = 0; it < iters; it++) {
        const int buf = it & 1;
        const bool more = (it + 1 < iters);
        if (more) { issue_tile((it + 1) * BK, buf ^ 1); CP_COMMIT(); }

#pragma unroll
        for (int ks = 0; ks < BK; ks += 16) {
            uint32_t af[2][MF][4], bf[2][NF][2];
#pragma unroll
            for (int s = 0; s < 2; s++) {
#pragma unroll
                for (int i = 0; i < MF; i++) {
                    int row = wm * WM + i * 16 + a_row_off;
                    uint32_t addr = asm_u32 +
                        (uint32_t)((((buf * 2 + s) * BM + row) * BKP + ks + a_col_off) * 2);
                    ldsm_x4(af[s][i], addr);
                }
#pragma unroll
                for (int jj = 0; jj < NF / 2; jj++) {
                    int row = wn * WN + jj * 16 + b_row_off;
                    uint32_t addr = bsm_u32 +
                        (uint32_t)((((buf * 2 + s) * BN + row) * BKP + ks + b_col_off) * 2);
                    uint32_t r[4];
                    ldsm_x4(r, addr);
                    bf[s][jj * 2 + 0][0] = r[0]; bf[s][jj * 2 + 0][1] = r[1];
                    bf[s][jj * 2 + 1][0] = r[2]; bf[s][jj * 2 + 1][1] = r[3];
                }
            }
            // term-major: all accumulators touched once per term -> no RAW chains
#pragma unroll
            for (int t = 0; t < 3; t++) {
                const int sa = (t == 2) ? 1 : 0;   // hh, hm, mh
                const int sb = (t == 1) ? 1 : 0;
#pragma unroll
                for (int i = 0; i < MF; i++)
#pragma unroll
                    for (int j = 0; j < NF; j++)
                        mma16816(acc[i][j], af[sa][i], bf[sb][j]);
            }
        }
        if (more) CP_WAIT0();
        __syncthreads();
    }

#pragma unroll
    for (int i = 0; i < MF; i++) {
        int r = m0 + wm * WM + i * 16 + g;
#pragma unroll
        for (int j = 0; j < NF; j++) {
            int c = n0 + wn * WN + j * 8 + t2;
            if (OUT == 2) {
                uint32_t h, mm;
                cvt_pair(acc[i][j][0], acc[i][j][1], h, mm);
                *(uint32_t*)&Chi[(size_t)r * ldc + c] = h;
                *(uint32_t*)&Cmid[(size_t)r * ldc + c] = mm;
                cvt_pair(acc[i][j][2], acc[i][j][3], h, mm);
                *(uint32_t*)&Chi[(size_t)(r + 8) * ldc + c] = h;
                *(uint32_t*)&Cmid[(size_t)(r + 8) * ldc + c] = mm;
            } else {
                float b0 = bias ? bias[c] : 0.0f;
                float b1 = bias ? bias[c + 1] : 0.0f;
                *(float2*)&Cf[(size_t)r * ldc + c] =
                    make_float2(acc[i][j][0] + b0, acc[i][j][1] + b1);
                *(float2*)&Cf[(size_t)(r + 8) * ldc + c] =
                    make_float2(acc[i][j][2] + b0, acc[i][j][3] + b1);
            }
        }
    }
}

// ---------------------------------------------------------------------------
// Fused attention (unchanged from R12 — proven at 1.58e-5).
// ---------------------------------------------------------------------------
#define BMQ 128
#define KT  64
#define NKT (SEQ/KT)
#define QP  72

__global__ __launch_bounds__(256, 2) void fused_attn(
    const __nv_bfloat16* __restrict__ qkv_hi,
    const __nv_bfloat16* __restrict__ qkv_mid,
    float* __restrict__ attn,
    __nv_bfloat16* __restrict__ ctx_hi,
    __nv_bfloat16* __restrict__ ctx_mid)
{
    extern __shared__ __nv_bfloat16 sm[];
    __nv_bfloat16* Qs = sm;                  // [2][128][72]
    __nv_bfloat16* Ks = Qs + 2 * BMQ * QP;   // [2][2][64][72]
    __nv_bfloat16* Vs = Ks + 4 * KT * QP;    // [2][2][64][72]
    const uint32_t qs_u = (uint32_t)__cvta_generic_to_shared(Qs);
    const uint32_t ks_u = (uint32_t)__cvta_generic_to_shared(Ks);
    const uint32_t vs_u = (uint32_t)__cvta_generic_to_shared(Vs);

    const int nb = blockIdx.x, h = blockIdx.y, b = blockIdx.z;
    const int tid = threadIdx.x, w = tid >> 5, lane = tid & 31;
    const int g = lane >> 2, t2 = (lane & 3) * 2;

    const size_t tokbase = (size_t)b * SEQ;
    const int qoff = h * DHEAD, koff = CDIM + h * DHEAD, voff = 2 * CDIM + h * DHEAD;

    const int a_row_off = ((lane >> 3) & 1) * 8 + (lane & 7);
    const int a_col_off = (lane >> 4) * 8;
    const int b_row_off = (lane >> 4) * 8 + (lane & 7);
    const int b_col_off = ((lane >> 3) & 1) * 8;
    const int bt_k_off  = ((lane >> 3) & 1) * 8 + (lane & 7);
    const int bt_n_off  = (lane >> 4) * 8;

    const int q_row = tid >> 1, q_seg = (tid & 1) * 32;    // Q staging
    const int kv_row = tid >> 2, kv_seg = (tid & 3) * 16;  // K/V staging

    // stage Q (once)
    {
        const __nv_bfloat16* qh = qkv_hi + (tokbase + nb * BMQ + q_row) * QKVC + qoff + q_seg;
        const __nv_bfloat16* qm = qkv_mid + (tokbase + nb * BMQ + q_row) * QKVC + qoff + q_seg;
        uint32_t d0 = qs_u + (uint32_t)(((0 * BMQ + q_row) * QP + q_seg) * 2);
        uint32_t d1 = qs_u + (uint32_t)(((1 * BMQ + q_row) * QP + q_seg) * 2);
#pragma unroll
        for (int e = 0; e < 32; e += 8) {
            cp_async16(d0 + 2 * e, qh + e);
            cp_async16(d1 + 2 * e, qm + e);
        }
    }

    auto issue_kv = [&](int kt2, int bb, bool withV) {
        const size_t tok = tokbase + kt2 * KT + kv_row;
        const __nv_bfloat16* kh = qkv_hi + tok * QKVC + koff + kv_seg;
        const __nv_bfloat16* km = qkv_mid + tok * QKVC + koff + kv_seg;
        uint32_t d0 = ks_u + (uint32_t)((((bb * 2 + 0) * KT + kv_row) * QP + kv_seg) * 2);
        uint32_t d1 = ks_u + (uint32_t)((((bb * 2 + 1) * KT + kv_row) * QP + kv_seg) * 2);
        cp_async16(d0, kh);      cp_async16(d0 + 16, kh + 8);
        cp_async16(d1, km);      cp_async16(d1 + 16, km + 8);
        if (withV) {
            const __nv_bfloat16* vh = qkv_hi + tok * QKVC + voff + kv_seg;
            const __nv_bfloat16* vm = qkv_mid + tok * QKVC + voff + kv_seg;
            uint32_t e0 = vs_u + (uint32_t)((((bb * 2 + 0) * KT + kv_row) * QP + kv_seg) * 2);
            uint32_t e1 = vs_u + (uint32_t)((((bb * 2 + 1) * KT + kv_row) * QP + kv_seg) * 2);
            cp_async16(e0, vh);      cp_async16(e0 + 16, vh + 8);
            cp_async16(e1, vm);      cp_async16(e1 + 16, vm + 8);
        }
    };

    float sacc[8][4];
    auto compute_S = [&](int buf) {
#pragma unroll
        for (int j = 0; j < 8; j++)
#pragma unroll
            for (int q = 0; q < 4; q++) sacc[j][q] = 0.0f;
#pragma unroll
        for (int ks = 0; ks < 4; ks++) {
            uint32_t af[2][4];
#pragma unroll
            for (int s = 0; s < 2; s++) {
                int row = w * 16 + a_row_off;
                ldsm_x4(af[s], qs_u +
                    (uint32_t)(((s * BMQ + row) * QP + ks * 16 + a_col_off) * 2));
            }
#pragma unroll
            for (int jj = 0; jj < 4; jj++) {
                uint32_t bh[4], bm[4];
                int row = jj * 16 + b_row_off;
                int col = ks * 16 + b_col_off;
                ldsm_x4(bh, ks_u + (uint32_t)((((buf * 2 + 0) * KT + row) * QP + col) * 2));
                ldsm_x4(bm, ks_u + (uint32_t)((((buf * 2 + 1) * KT + row) * QP + col) * 2));
                uint32_t b0h[2] = { bh[0], bh[1] }, b1h[2] = { bh[2], bh[3] };
                uint32_t b0m[2] = { bm[0], bm[1] }, b1m[2] = { bm[2], bm[3] };
                mma16816(sacc[jj * 2 + 0], af[0], b0h);
                mma16816(sacc[jj * 2 + 0], af[0], b0m);
                mma16816(sacc[jj * 2 + 0], af[1], b0h);
                mma16816(sacc[jj * 2 + 1], af[0], b1h);
                mma16816(sacc[jj * 2 + 1], af[0], b1m);
                mma16816(sacc[jj * 2 + 1], af[1], b1h);
            }
        }
    };

    float U[8][4];
#pragma unroll
    for (int j = 0; j < 8; j++)
#pragma unroll
        for (int q = 0; q < 4; q++) U[j][q] = 0.0f;
    float rs0 = 0.0f, rs1 = 0.0f;

    // ---------------- Phase 1 ----------------
    issue_kv(0, 0, true);
    CP_COMMIT(); CP_WAIT0(); __syncthreads();

    for (int kt = 0; kt < NKT; kt++) {
        const int buf = kt & 1;
        const bool more = (kt + 1 < NKT);
        if (more) { issue_kv(kt + 1, buf ^ 1, true); CP_COMMIT(); }

        compute_S(buf);

#pragma unroll
        for (int j = 0; j < 8; j++) {
            sacc[j][0] = __expf(0.125f * sacc[j][0]);
            sacc[j][1] = __expf(0.125f * sacc[j][1]);
            sacc[j][2] = __expf(0.125f * sacc[j][2]);
            sacc[j][3] = __expf(0.125f * sacc[j][3]);
            rs0 += sacc[j][0] + sacc[j][1];
            rs1 += sacc[j][2] + sacc[j][3];
        }

        // U += E @ V  (C-frag -> A-frag reuse)
#pragma unroll
        for (int ks = 0; ks < 4; ks++) {
            uint32_t ah[4], am[4];
            cvt_pair(sacc[2 * ks][0],     sacc[2 * ks][1],     ah[0], am[0]);
            cvt_pair(sacc[2 * ks][2],     sacc[2 * ks][3],     ah[1], am[1]);
            cvt_pair(sacc[2 * ks + 1][0], sacc[2 * ks + 1][1], ah[2], am[2]);
            cvt_pair(sacc[2 * ks + 1][2], sacc[2 * ks + 1][3], ah[3], am[3]);
#pragma unroll
            for (int jv = 0; jv < 4; jv++) {
                uint32_t rh[4], rm[4];
                int kR = ks * 16 + bt_k_off;
                int nB = jv * 16 + bt_n_off;
                ldsm_x4_t(rh, vs_u + (uint32_t)((((buf * 2 + 0) * KT + kR) * QP + nB) * 2));
                ldsm_x4_t(rm, vs_u + (uint32_t)((((buf * 2 + 1) * KT + kR) * QP + nB) * 2));
                uint32_t bh0[2] = { rh[0], rh[1] }, bh1[2] = { rh[2], rh[3] };
                uint32_t bm0[2] = { rm[0], rm[1] }, bm1[2] = { rm[2], rm[3] };
                mma16816(U[jv * 2 + 0], ah, bh0);
                mma16816(U[jv * 2 + 0], ah, bm0);
                mma16816(U[jv * 2 + 0], am, bh0);
                mma16816(U[jv * 2 + 1], ah, bh1);
                mma16816(U[jv * 2 + 1], ah, bm1);
                mma16816(U[jv * 2 + 1], am, bh1);
            }
        }

        if (more) CP_WAIT0();
        __syncthreads();
    }

    rs0 += __shfl_xor_sync(0xffffffffu, rs0, 1);
    rs0 += __shfl_xor_sync(0xffffffffu, rs0, 2);
    rs1 += __shfl_xor_sync(0xffffffffu, rs1, 1);
    rs1 += __shfl_xor_sync(0xffffffffu, rs1, 2);
    const float inv0 = 1.0f / rs0;
    const float inv1 = 1.0f / rs1;

    // ctx = U * inv -> hi/mid planes
    {
        const size_t tok = tokbase + nb * BMQ + w * 16 + g;
        __nv_bfloat16* ch = ctx_hi + tok * CDIM + h * DHEAD;
        __nv_bfloat16* cm = ctx_mid + tok * CDIM + h * DHEAD;
#pragma unroll
        for (int jv = 0; jv < 8; jv++) {
            int c = jv * 8 + t2;
            uint32_t hh, mm;
            cvt_pair(U[jv][0] * inv0, U[jv][1] * inv0, hh, mm);
            *(uint32_t*)&ch[c] = hh;
            *(uint32_t*)&cm[c] = mm;
            cvt_pair(U[jv][2] * inv1, U[jv][3] * inv1, hh, mm);
            *(uint32_t*)&ch[8 * CDIM + c] = hh;
            *(uint32_t*)&cm[8 * CDIM + c] = mm;
        }
    }

    // ---------------- Phase 2: recompute S, write P ----------------
    issue_kv(0, 0, false);
    CP_COMMIT(); CP_WAIT0(); __syncthreads();

    float* dst0 = attn + ((size_t)(b * HEADS + h) * SEQ + nb * BMQ + w * 16 + g) * SEQ;
    float* dst1 = dst0 + 8 * SEQ;

    for (int kt = 0; kt < NKT; kt++) {
        const int buf = kt & 1;
        const bool more = (kt + 1 < NKT);
        if (more) { issue_kv(kt + 1, buf ^ 1, false); CP_COMMIT(); }

        compute_S(buf);

#pragma unroll
        for (int j = 0; j < 8; j++) {
            int c = kt * KT + j * 8 + t2;
            float e0 = __expf(0.125f * sacc[j][0]);
            float e1 = __expf(0.125f * sacc[j][1]);
            float e2 = __expf(0.125f * sacc[j][2]);
            float e3 = __expf(0.125f * sacc[j][3]);
            *(float2*)&dst0[c] = make_float2(e0 * inv0, e1 * inv0);
            *(float2*)&dst1[c] = make_float2(e2 * inv1, e3 * inv1);
        }

        if (more) CP_WAIT0();
        __syncthreads();
    }
}

// ---------------------------------------------------------------------------
extern "C" void kernel_launch(void* const* d_in, const int* in_sizes, int n_in,
                              void* d_out, int out_size)
{
    const float* x      = (const float*)d_in[0];
    const float* qkv_w  = (const float*)d_in[1];
    const float* proj_w = (const float*)d_in[2];
    const float* proj_b = (const float*)d_in[3];

    float* out_proj = (float*)d_out;
    float* out_attn = (float*)d_out + (size_t)MTOK * CDIM;

    __nv_bfloat16 *x_hi, *x_mid, *wq_hi, *wq_mid, *wp_hi, *wp_mid;
    __nv_bfloat16 *qkv_hi, *qkv_mid, *ctx_hi, *ctx_mid;
    cudaGetSymbolAddress((void**)&x_hi,   g_x_hi);
    cudaGetSymbolAddress((void**)&x_mid,  g_x_mid);
    cudaGetSymbolAddress((void**)&wq_hi,  g_wqkv_hi);
    cudaGetSymbolAddress((void**)&wq_mid, g_wqkv_mid);
    cudaGetSymbolAddress((void**)&wp_hi,  g_wproj_hi);
    cudaGetSymbolAddress((void**)&wp_mid, g_wproj_mid);
    cudaGetSymbolAddress((void**)&qkv_hi, g_qkv_hi);
    cudaGetSymbolAddress((void**)&qkv_mid,g_qkv_mid);
    cudaGetSymbolAddress((void**)&ctx_hi, g_ctx_hi);
    cudaGetSymbolAddress((void**)&ctx_mid,g_ctx_mid);

    constexpr int SM_KC = (4 * 128 * 40 + 4 * 128 * 40) * 2;                // 81920 B
    constexpr int SM_FA = (2 * BMQ * QP + 4 * KT * QP + 4 * KT * QP) * 2;   // 110592 B

    cudaFuncSetAttribute((const void*)gemm3<2>,
                         cudaFuncAttributeMaxDynamicSharedMemorySize, SM_KC);
    cudaFuncSetAttribute((const void*)gemm3<0>,
                         cudaFuncAttributeMaxDynamicSharedMemorySize, SM_KC);
    cudaFuncSetAttribute((const void*)fused_attn,
                         cudaFuncAttributeMaxDynamicSharedMemorySize, SM_FA);

    // 0) split inputs to hi/mid planes
    {
        int total = N4_X + N4_WQ + N4_WP;
        prep_kernel<<<(total + 255) / 256, 256>>>(
            x, qkv_w, proj_w, x_hi, x_mid, wq_hi, wq_mid, wp_hi, wp_mid);
    }

    // 1) QKV GEMM -> split planes
    gemm3<2><<<dim3(QKVC / 128, MTOK / 128), 256, SM_KC>>>(
        x_hi, x_mid, CDIM, wq_hi, wq_mid, CDIM,
        nullptr, qkv_hi, qkv_mid, QKVC, CDIM, nullptr);

    // 2) fused attention: S + softmax + attn write + PV
    fused_attn<<<dim3(SEQ / BMQ, HEADS, BATCH), 256, SM_FA>>>(
        qkv_hi, qkv_mid, out_attn, ctx_hi, ctx_mid);

    // 3) proj: ctx @ proj_w^T + bias -> out
    gemm3<0><<<dim3(CDIM / 128, MTOK / 128), 256, SM_KC>>>(
        ctx_hi, ctx_mid, CDIM, wp_hi, wp_mid, CDIM,
        out_proj, nullptr, nullptr, CDIM, CDIM, proj_b);
}

// round 17
// speedup vs baseline: 1.3989x; 1.3825x over previous
#include <cuda_runtime.h>
#include <cuda_fp16.h>
#include <cstdint>
#include <cstddef>

#define BATCH 8
#define SEQ   1024
#define CDIM  768
#define HEADS 12
#define MTOK  (BATCH*SEQ)      // 8192
#define QKVC  (3*CDIM)         // 2304
#define DHEAD 64

// Persistent scratch (device globals — allocation is forbidden)
// fp16 planes. B-side operands only ever need the hi plane.
__device__ __half g_x_hi   [(size_t)MTOK * CDIM];
__device__ __half g_x_mid  [(size_t)MTOK * CDIM];
__device__ __half g_wqkv_hi [(size_t)QKVC * CDIM];
__device__ __half g_wproj_hi [(size_t)CDIM * CDIM];
__device__ __half g_qkv_hi [(size_t)MTOK * QKVC];
__device__ __half g_qkv_mid[(size_t)MTOK * QKVC];
__device__ __half g_ctx_hi [(size_t)MTOK * CDIM];
__device__ __half g_ctx_mid[(size_t)MTOK * CDIM];

// ---------------------------------------------------------------------------
__device__ __forceinline__ void mma16816(float* d, const uint32_t* a, const uint32_t* b)
{
    asm volatile(
        "mma.sync.aligned.m16n8k16.row.col.f32.f16.f16.f32 "
        "{%0,%1,%2,%3},{%4,%5,%6,%7},{%8,%9},{%0,%1,%2,%3};\n"
        : "+f"(d[0]), "+f"(d[1]), "+f"(d[2]), "+f"(d[3])
        : "r"(a[0]), "r"(a[1]), "r"(a[2]), "r"(a[3]), "r"(b[0]), "r"(b[1]));
}

__device__ __forceinline__ void ldsm_x4(uint32_t* r, uint32_t saddr)
{
    asm volatile("ldmatrix.sync.aligned.m8n8.x4.shared.b16 {%0,%1,%2,%3}, [%4];"
        : "=r"(r[0]), "=r"(r[1]), "=r"(r[2]), "=r"(r[3]) : "r"(saddr));
}

__device__ __forceinline__ void ldsm_x4_t(uint32_t* r, uint32_t saddr)
{
    asm volatile("ldmatrix.sync.aligned.m8n8.x4.trans.shared.b16 {%0,%1,%2,%3}, [%4];"
        : "=r"(r[0]), "=r"(r[1]), "=r"(r[2]), "=r"(r[3]) : "r"(saddr));
}

__device__ __forceinline__ void cp_async16(uint32_t saddr, const void* gptr)
{
    asm volatile("cp.async.cg.shared.global [%0], [%1], 16;"
        :: "r"(saddr), "l"(gptr));
}
#define CP_COMMIT() asm volatile("cp.async.commit_group;" ::: "memory")
#define CP_WAIT0()  asm volatile("cp.async.wait_group 0;" ::: "memory")

// fp32 pair -> (hi, mid) fp16x2 pairs
__device__ __forceinline__ void cvt_pair(float x, float y, uint32_t& hi, uint32_t& mid)
{
    __half2 h = __floats2half2_rn(x, y);
    float rx = x - __half2float(__low2half(h));
    float ry = y - __half2float(__high2half(h));
    __half2 m = __floats2half2_rn(rx, ry);
    hi  = *reinterpret_cast<uint32_t*>(&h);
    mid = *reinterpret_cast<uint32_t*>(&m);
}

// ---------------------------------------------------------------------------
// Fused prep: x -> hi+mid planes; wqkv/wproj -> hi plane only. One launch.
// ---------------------------------------------------------------------------
#define N4_X   (MTOK * CDIM / 4)
#define N4_WQ  (QKVC * CDIM / 4)
#define N4_WP  (CDIM * CDIM / 4)

__global__ __launch_bounds__(256) void prep_kernel(
    const float* __restrict__ x, const float* __restrict__ wq,
    const float* __restrict__ wp,
    __half* __restrict__ x_hi, __half* __restrict__ x_mid,
    __half* __restrict__ wq_hi, __half* __restrict__ wp_hi)
{
    int i = blockIdx.x * blockDim.x + threadIdx.x;
    if (i < N4_X) {
        float4 v = ((const float4*)x)[i];
        uint32_t h0, m0, h1, m1;
        cvt_pair(v.x, v.y, h0, m0);
        cvt_pair(v.z, v.w, h1, m1);
        ((uint2*)x_hi)[i]  = make_uint2(h0, h1);
        ((uint2*)x_mid)[i] = make_uint2(m0, m1);
    } else if (i < N4_X + N4_WQ) {
        int j = i - N4_X;
        float4 v = ((const float4*)wq)[j];
        __half2 h0 = __floats2half2_rn(v.x, v.y);
        __half2 h1 = __floats2half2_rn(v.z, v.w);
        ((uint2*)wq_hi)[j] = make_uint2(*(uint32_t*)&h0, *(uint32_t*)&h1);
    } else if (i < N4_X + N4_WQ + N4_WP) {
        int j = i - N4_X - N4_WQ;
        float4 v = ((const float4*)wp)[j];
        __half2 h0 = __floats2half2_rn(v.x, v.y);
        __half2 h1 = __floats2half2_rn(v.z, v.w);
        ((uint2*)wp_hi)[j] = make_uint2(*(uint32_t*)&h0, *(uint32_t*)&h1);
    }
}

// ---------------------------------------------------------------------------
// GEMM, fp16 2-term split: C = (Ah+Am) @ Bh^T  (2 MMAs per fragment).
// A: hi+mid planes [M,K] k-contig. B: hi plane [N,K] k-contig.
// OUT=0: fp32 + bias.  OUT=2: hi/mid fp16 planes.
// ---------------------------------------------------------------------------
template<int OUT>
__global__ __launch_bounds__(256, 2) void gemm3(
    const __half* __restrict__ Ahi, const __half* __restrict__ Amid, int lda,
    const __half* __restrict__ Bhi, int ldb,
    float* __restrict__ Cf, __half* __restrict__ Chi, __half* __restrict__ Cmid,
    int ldc, int K, const float* __restrict__ bias)
{
    constexpr int BM = 128, BN = 128, WM = 64, WN = 32;
    constexpr int BK = 32, BKP = 40;
    constexpr int MW = BM / WM, MF = WM / 16, NF = WN / 8;

    extern __shared__ __half sm[];
    __half* Asm = sm;                       // [2buf][2pl][BM][BKP]
    __half* Bsm = sm + 4 * BM * BKP;        // [2buf][BN][BKP]
    const uint32_t asm_u32 = (uint32_t)__cvta_generic_to_shared(Asm);
    const uint32_t bsm_u32 = (uint32_t)__cvta_generic_to_shared(Bsm);

    const int m0 = blockIdx.y * BM, n0 = blockIdx.x * BN;
    const int tid = threadIdx.x, w = tid >> 5, lane = tid & 31;
    const int wm = w % MW, wn = w / MW;
    const int g = lane >> 2, t2 = (lane & 3) * 2;

    const int a_row_off = ((lane >> 3) & 1) * 8 + (lane & 7);
    const int a_col_off = (lane >> 4) * 8;
    const int b_row_off = (lane >> 4) * 8 + (lane & 7);
    const int b_col_off = ((lane >> 3) & 1) * 8;

    float acc[MF][NF][4];
#pragma unroll
    for (int i = 0; i < MF; i++)
#pragma unroll
        for (int j = 0; j < NF; j++)
#pragma unroll
            for (int q = 0; q < 4; q++) acc[i][j][q] = 0.0f;

    const int a_row = tid >> 1, a_seg = (tid & 1) * 16;

    auto issue_tile = [&](int kt, int bb) {
        const __half* ph = Ahi + (size_t)(m0 + a_row) * lda + kt + a_seg;
        const __half* pm = Amid + (size_t)(m0 + a_row) * lda + kt + a_seg;
        uint32_t d0 = asm_u32 + (uint32_t)((((bb * 2 + 0) * BM + a_row) * BKP + a_seg) * 2);
        uint32_t d1 = asm_u32 + (uint32_t)((((bb * 2 + 1) * BM + a_row) * BKP + a_seg) * 2);
        cp_async16(d0, ph);      cp_async16(d0 + 16, ph + 8);
        cp_async16(d1, pm);      cp_async16(d1 + 16, pm + 8);
        const __half* qh = Bhi + (size_t)(n0 + a_row) * ldb + kt + a_seg;
        uint32_t e0 = bsm_u32 + (uint32_t)(((bb * BN + a_row) * BKP + a_seg) * 2);
        cp_async16(e0, qh);      cp_async16(e0 + 16, qh + 8);
    };

    const int iters = K / BK;
    issue_tile(0, 0);
    CP_COMMIT(); CP_WAIT0(); __syncthreads();

    for (int it = 0; it < iters; it++) {
        const int buf = it & 1;
        const bool more = (it + 1 < iters);
        if (more) { issue_tile((it + 1) * BK, buf ^ 1); CP_COMMIT(); }

#pragma unroll
        for (int ks = 0; ks < BK; ks += 16) {
            uint32_t af[2][MF][4], bf[NF][2];
#pragma unroll
            for (int s = 0; s < 2; s++)
#pragma unroll
                for (int i = 0; i < MF; i++) {
                    int row = wm * WM + i * 16 + a_row_off;
                    uint32_t addr = asm_u32 +
                        (uint32_t)((((buf * 2 + s) * BM + row) * BKP + ks + a_col_off) * 2);
                    ldsm_x4(af[s][i], addr);
                }
#pragma unroll
            for (int jj = 0; jj < NF / 2; jj++) {
                int row = wn * WN + jj * 16 + b_row_off;
                uint32_t addr = bsm_u32 +
                    (uint32_t)(((buf * BN + row) * BKP + ks + b_col_off) * 2);
                uint32_t r[4];
                ldsm_x4(r, addr);
                bf[jj * 2 + 0][0] = r[0]; bf[jj * 2 + 0][1] = r[1];
                bf[jj * 2 + 1][0] = r[2]; bf[jj * 2 + 1][1] = r[3];
            }
            // 2-term: hh then mh, term-major (no RAW chains)
#pragma unroll
            for (int s = 0; s < 2; s++)
#pragma unroll
                for (int i = 0; i < MF; i++)
#pragma unroll
                    for (int j = 0; j < NF; j++)
                        mma16816(acc[i][j], af[s][i], bf[j]);
        }
        if (more) CP_WAIT0();
        __syncthreads();
    }

#pragma unroll
    for (int i = 0; i < MF; i++) {
        int r = m0 + wm * WM + i * 16 + g;
#pragma unroll
        for (int j = 0; j < NF; j++) {
            int c = n0 + wn * WN + j * 8 + t2;
            if (OUT == 2) {
                uint32_t h, mm;
                cvt_pair(acc[i][j][0], acc[i][j][1], h, mm);
                *(uint32_t*)&Chi[(size_t)r * ldc + c] = h;
                *(uint32_t*)&Cmid[(size_t)r * ldc + c] = mm;
                cvt_pair(acc[i][j][2], acc[i][j][3], h, mm);
                *(uint32_t*)&Chi[(size_t)(r + 8) * ldc + c] = h;
                *(uint32_t*)&Cmid[(size_t)(r + 8) * ldc + c] = mm;
            } else {
                float b0 = bias ? bias[c] : 0.0f;
                float b1 = bias ? bias[c + 1] : 0.0f;
                *(float2*)&Cf[(size_t)r * ldc + c] =
                    make_float2(acc[i][j][0] + b0, acc[i][j][1] + b1);
                *(float2*)&Cf[(size_t)(r + 8) * ldc + c] =
                    make_float2(acc[i][j][2] + b0, acc[i][j][3] + b1);
            }
        }
    }
}

// ---------------------------------------------------------------------------
// Fused attention (R12 structure; fp16 2-term: S = (Qh+Qm)·Kh, U = (Eh+Em)·Vh).
// ---------------------------------------------------------------------------
#define BMQ 128
#define KT  64
#define NKT (SEQ/KT)
#define QP  72

__global__ __launch_bounds__(256, 2) void fused_attn(
    const __half* __restrict__ qkv_hi,
    const __half* __restrict__ qkv_mid,
    float* __restrict__ attn,
    __half* __restrict__ ctx_hi,
    __half* __restrict__ ctx_mid)
{
    extern __shared__ __half sm[];
    __half* Qs = sm;                  // [2pl][128][72]
    __half* Ks = Qs + 2 * BMQ * QP;   // [2buf][64][72]  (hi only)
    __half* Vs = Ks + 2 * KT * QP;    // [2buf][64][72]  (hi only)
    const uint32_t qs_u = (uint32_t)__cvta_generic_to_shared(Qs);
    const uint32_t ks_u = (uint32_t)__cvta_generic_to_shared(Ks);
    const uint32_t vs_u = (uint32_t)__cvta_generic_to_shared(Vs);

    const int nb = blockIdx.x, h = blockIdx.y, b = blockIdx.z;
    const int tid = threadIdx.x, w = tid >> 5, lane = tid & 31;
    const int g = lane >> 2, t2 = (lane & 3) * 2;

    const size_t tokbase = (size_t)b * SEQ;
    const int qoff = h * DHEAD, koff = CDIM + h * DHEAD, voff = 2 * CDIM + h * DHEAD;

    const int a_row_off = ((lane >> 3) & 1) * 8 + (lane & 7);
    const int a_col_off = (lane >> 4) * 8;
    const int b_row_off = (lane >> 4) * 8 + (lane & 7);
    const int b_col_off = ((lane >> 3) & 1) * 8;
    const int bt_k_off  = ((lane >> 3) & 1) * 8 + (lane & 7);
    const int bt_n_off  = (lane >> 4) * 8;

    const int q_row = tid >> 1, q_seg = (tid & 1) * 32;    // Q staging
    const int kv_row = tid >> 2, kv_seg = (tid & 3) * 16;  // K/V staging

    // stage Q (once, both planes)
    {
        const __half* qh = qkv_hi + (tokbase + nb * BMQ + q_row) * QKVC + qoff + q_seg;
        const __half* qm = qkv_mid + (tokbase + nb * BMQ + q_row) * QKVC + qoff + q_seg;
        uint32_t d0 = qs_u + (uint32_t)(((0 * BMQ + q_row) * QP + q_seg) * 2);
        uint32_t d1 = qs_u + (uint32_t)(((1 * BMQ + q_row) * QP + q_seg) * 2);
#pragma unroll
        for (int e = 0; e < 32; e += 8) {
            cp_async16(d0 + 2 * e, qh + e);
            cp_async16(d1 + 2 * e, qm + e);
        }
    }

    auto issue_kv = [&](int kt2, int bb, bool withV) {
        const size_t tok = tokbase + kt2 * KT + kv_row;
        const __half* kh = qkv_hi + tok * QKVC + koff + kv_seg;
        uint32_t d0 = ks_u + (uint32_t)(((bb * KT + kv_row) * QP + kv_seg) * 2);
        cp_async16(d0, kh);      cp_async16(d0 + 16, kh + 8);
        if (withV) {
            const __half* vh = qkv_hi + tok * QKVC + voff + kv_seg;
            uint32_t e0 = vs_u + (uint32_t)(((bb * KT + kv_row) * QP + kv_seg) * 2);
            cp_async16(e0, vh);      cp_async16(e0 + 16, vh + 8);
        }
    };

    float sacc[8][4];
    auto compute_S = [&](int buf) {
#pragma unroll
        for (int j = 0; j < 8; j++)
#pragma unroll
            for (int q = 0; q < 4; q++) sacc[j][q] = 0.0f;
#pragma unroll
        for (int ks = 0; ks < 4; ks++) {
            uint32_t af[2][4];
#pragma unroll
            for (int s = 0; s < 2; s++) {
                int row = w * 16 + a_row_off;
                ldsm_x4(af[s], qs_u +
                    (uint32_t)(((s * BMQ + row) * QP + ks * 16 + a_col_off) * 2));
            }
#pragma unroll
            for (int jj = 0; jj < 4; jj++) {
                uint32_t bh[4];
                int row = jj * 16 + b_row_off;
                int col = ks * 16 + b_col_off;
                ldsm_x4(bh, ks_u + (uint32_t)(((buf * KT + row) * QP + col) * 2));
                uint32_t b0h[2] = { bh[0], bh[1] }, b1h[2] = { bh[2], bh[3] };
                mma16816(sacc[jj * 2 + 0], af[0], b0h);
                mma16816(sacc[jj * 2 + 0], af[1], b0h);
                mma16816(sacc[jj * 2 + 1], af[0], b1h);
                mma16816(sacc[jj * 2 + 1], af[1], b1h);
            }
        }
    };

    float U[8][4];
#pragma unroll
    for (int j = 0; j < 8; j++)
#pragma unroll
        for (int q = 0; q < 4; q++) U[j][q] = 0.0f;
    float rs0 = 0.0f, rs1 = 0.0f;

    // ---------------- Phase 1 ----------------
    issue_kv(0, 0, true);
    CP_COMMIT(); CP_WAIT0(); __syncthreads();

    for (int kt = 0; kt < NKT; kt++) {
        const int buf = kt & 1;
        const bool more = (kt + 1 < NKT);
        if (more) { issue_kv(kt + 1, buf ^ 1, true); CP_COMMIT(); }

        compute_S(buf);

#pragma unroll
        for (int j = 0; j < 8; j++) {
            sacc[j][0] = __expf(0.125f * sacc[j][0]);
            sacc[j][1] = __expf(0.125f * sacc[j][1]);
            sacc[j][2] = __expf(0.125f * sacc[j][2]);
            sacc[j][3] = __expf(0.125f * sacc[j][3]);
            rs0 += sacc[j][0] + sacc[j][1];
            rs1 += sacc[j][2] + sacc[j][3];
        }

        // U += E @ Vh  (C-frag -> A-frag reuse; 2-term)
#pragma unroll
        for (int ks = 0; ks < 4; ks++) {
            uint32_t ah[4], am[4];
            cvt_pair(sacc[2 * ks][0],     sacc[2 * ks][1],     ah[0], am[0]);
            cvt_pair(sacc[2 * ks][2],     sacc[2 * ks][3],     ah[1], am[1]);
            cvt_pair(sacc[2 * ks + 1][0], sacc[2 * ks + 1][1], ah[2], am[2]);
            cvt_pair(sacc[2 * ks + 1][2], sacc[2 * ks + 1][3], ah[3], am[3]);
#pragma unroll
            for (int jv = 0; jv < 4; jv++) {
                uint32_t rh[4];
                int kR = ks * 16 + bt_k_off;
                int nB = jv * 16 + bt_n_off;
                ldsm_x4_t(rh, vs_u + (uint32_t)(((buf * KT + kR) * QP + nB) * 2));
                uint32_t bh0[2] = { rh[0], rh[1] }, bh1[2] = { rh[2], rh[3] };
                mma16816(U[jv * 2 + 0], ah, bh0);
                mma16816(U[jv * 2 + 0], am, bh0);
                mma16816(U[jv * 2 + 1], ah, bh1);
                mma16816(U[jv * 2 + 1], am, bh1);
            }
        }

        if (more) CP_WAIT0();
        __syncthreads();
    }

    rs0 += __shfl_xor_sync(0xffffffffu, rs0, 1);
    rs0 += __shfl_xor_sync(0xffffffffu, rs0, 2);
    rs1 += __shfl_xor_sync(0xffffffffu, rs1, 1);
    rs1 += __shfl_xor_sync(0xffffffffu, rs1, 2);
    const float inv0 = 1.0f / rs0;
    const float inv1 = 1.0f / rs1;

    // ctx = U * inv -> hi/mid fp16 planes
    {
        const size_t tok = tokbase + nb * BMQ + w * 16 + g;
        __half* ch = ctx_hi + tok * CDIM + h * DHEAD;
        __half* cm = ctx_mid + tok * CDIM + h * DHEAD;
#pragma unroll
        for (int jv = 0; jv < 8; jv++) {
            int c = jv * 8 + t2;
            uint32_t hh, mm;
            cvt_pair(U[jv][0] * inv0, U[jv][1] * inv0, hh, mm);
            *(uint32_t*)&ch[c] = hh;
            *(uint32_t*)&cm[c] = mm;
            cvt_pair(U[jv][2] * inv1, U[jv][3] * inv1, hh, mm);
            *(uint32_t*)&ch[8 * CDIM + c] = hh;
            *(uint32_t*)&cm[8 * CDIM + c] = mm;
        }
    }

    // ---------------- Phase 2: recompute S, write P ----------------
    issue_kv(0, 0, false);
    CP_COMMIT(); CP_WAIT0(); __syncthreads();

    float* dst0 = attn + ((size_t)(b * HEADS + h) * SEQ + nb * BMQ + w * 16 + g) * SEQ;
    float* dst1 = dst0 + 8 * SEQ;

    for (int kt = 0; kt < NKT; kt++) {
        const int buf = kt & 1;
        const bool more = (kt + 1 < NKT);
        if (more) { issue_kv(kt + 1, buf ^ 1, false); CP_COMMIT(); }

        compute_S(buf);

#pragma unroll
        for (int j = 0; j < 8; j++) {
            int c = kt * KT + j * 8 + t2;
            float e0 = __expf(0.125f * sacc[j][0]);
            float e1 = __expf(0.125f * sacc[j][1]);
            float e2 = __expf(0.125f * sacc[j][2]);
            float e3 = __expf(0.125f * sacc[j][3]);
            *(float2*)&dst0[c] = make_float2(e0 * inv0, e1 * inv0);
            *(float2*)&dst1[c] = make_float2(e2 * inv1, e3 * inv1);
        }

        if (more) CP_WAIT0();
        __syncthreads();
    }
}

// ---------------------------------------------------------------------------
extern "C" void kernel_launch(void* const* d_in, const int* in_sizes, int n_in,
                              void* d_out, int out_size)
{
    const float* x      = (const float*)d_in[0];
    const float* qkv_w  = (const float*)d_in[1];
    const float* proj_w = (const float*)d_in[2];
    const float* proj_b = (const float*)d_in[3];

    float* out_proj = (float*)d_out;
    float* out_attn = (float*)d_out + (size_t)MTOK * CDIM;

    __half *x_hi, *x_mid, *wq_hi, *wp_hi;
    __half *qkv_hi, *qkv_mid, *ctx_hi, *ctx_mid;
    cudaGetSymbolAddress((void**)&x_hi,   g_x_hi);
    cudaGetSymbolAddress((void**)&x_mid,  g_x_mid);
    cudaGetSymbolAddress((void**)&wq_hi,  g_wqkv_hi);
    cudaGetSymbolAddress((void**)&wp_hi,  g_wproj_hi);
    cudaGetSymbolAddress((void**)&qkv_hi, g_qkv_hi);
    cudaGetSymbolAddress((void**)&qkv_mid,g_qkv_mid);
    cudaGetSymbolAddress((void**)&ctx_hi, g_ctx_hi);
    cudaGetSymbolAddress((void**)&ctx_mid,g_ctx_mid);

    constexpr int SM_KC = (4 * 128 * 40 + 2 * 128 * 40) * 2;                // 61440 B
    constexpr int SM_FA = (2 * BMQ * QP + 2 * KT * QP + 2 * KT * QP) * 2;   // 73728 B

    cudaFuncSetAttribute((const void*)gemm3<2>,
                         cudaFuncAttributeMaxDynamicSharedMemorySize, SM_KC);
    cudaFuncSetAttribute((const void*)gemm3<0>,
                         cudaFuncAttributeMaxDynamicSharedMemorySize, SM_KC);
    cudaFuncSetAttribute((const void*)fused_attn,
                         cudaFuncAttributeMaxDynamicSharedMemorySize, SM_FA);

    // 0) split inputs (x -> hi+mid; weights -> hi only)
    {
        int total = N4_X + N4_WQ + N4_WP;
        prep_kernel<<<(total + 255) / 256, 256>>>(
            x, qkv_w, proj_w, x_hi, x_mid, wq_hi, wp_hi);
    }

    // 1) QKV GEMM -> split planes
    gemm3<2><<<dim3(QKVC / 128, MTOK / 128), 256, SM_KC>>>(
        x_hi, x_mid, CDIM, wq_hi, CDIM,
        nullptr, qkv_hi, qkv_mid, QKVC, CDIM, nullptr);

    // 2) fused attention: S + softmax + attn write + PV
    fused_attn<<<dim3(SEQ / BMQ, HEADS, BATCH), 256, SM_FA>>>(
        qkv_hi, qkv_mid, out_attn, ctx_hi, ctx_mid);

    // 3) proj: ctx @ proj_w^T + bias -> out
    gemm3<0><<<dim3(CDIM / 128, MTOK / 128), 256, SM_KC>>>(
        ctx_hi, ctx_mid, CDIM, wp_hi, CDIM,
        out_proj, nullptr, nullptr, CDIM, CDIM, proj_b);
}